// round 15
// baseline (speedup 1.0000x reference)
#include <cuda_runtime.h>
#include <cuda_fp16.h>
#include <mma.h>
#include <math.h>

using namespace nvcuda;

#define N_NODES_MAX 100000
#define E_MAX 3200000
#define IN_DIM 512
#define HID 256
#define SCAN_B 256

// GEMM tiles: full-width N so A is read exactly once; BM=128 halves B-traffic.
#define BM 128
#define BN 256
#define BK 32
#define APAD 8
#define BPAD 8

// Static device scratch (allocation-free). bufH padded by 64 rows so the
// head kernel's last block can issue full wmma tile loads safely.
__device__ __half g_bufS[(size_t)N_NODES_MAX * HID];          // fp16 support S
__device__ __half g_bufH[(size_t)(N_NODES_MAX + 64) * HID];   // fp16 H, then L
__device__ __half g_W1h[IN_DIM * HID];                        // fp16 W1
__device__ __half g_W2h[HID * HID];                           // fp16 W2
__device__ int    g_counts[N_NODES_MAX];
__device__ int    g_rowPtr[N_NODES_MAX + 1];
__device__ int    g_blockSums[(N_NODES_MAX + SCAN_B - 1) / SCAN_B + 1];
__device__ unsigned g_csr[E_MAX];   // packed edge: val_fp16_bits[14:0] << 17 | col[16:0]

// ---------------------------------------------------------------------------
// One-shot fp32 -> fp16 weight conversion (W1 then W2).
// ---------------------------------------------------------------------------
__global__ void convert_w_kernel(const float* __restrict__ W1,
                                 const float* __restrict__ W2,
                                 __half* __restrict__ W1h,
                                 __half* __restrict__ W2h)
{
    const int i = blockIdx.x * blockDim.x + threadIdx.x;
    if (i < IN_DIM * HID) W1h[i] = __float2half(W1[i]);
    if (i < HID * HID)    W2h[i] = __float2half(W2[i]);
}

// ---------------------------------------------------------------------------
// Tensor-core GEMM: C[M,N] = half(A[M,K] @ B[K,N]); A fp32 or fp16 (converted
// in the loader), B fp16 (pre-converted weights), fp32 accumulate, fp16 out.
// BM=128, BN=256, BK=32, 512 threads = 16 warps (4 along M x 4 along N).
// ---------------------------------------------------------------------------
template <typename TA>
__global__ __launch_bounds__(512) void gemm_tc_kernel(
    const TA* __restrict__ A, const __half* __restrict__ B,
    __half* __restrict__ C, int M, int K, int N)
{
    __shared__ __half As[BM][BK + APAD];
    __shared__ __half Bs[BK][BN + BPAD];
    __shared__ float  stage[16][16 * 16];

    const int tid = threadIdx.x;
    const int wid = tid >> 5;
    const int lane = tid & 31;
    const int warpM = wid & 3;          // 0..3 -> 32 rows each
    const int warpN = wid >> 2;         // 0..3 -> 64 cols each
    const int rowBase = blockIdx.x * BM;

    wmma::fragment<wmma::accumulator, 16, 16, 16, float> acc[2][4];
#pragma unroll
    for (int i = 0; i < 2; i++)
#pragma unroll
        for (int j = 0; j < 4; j++) wmma::fill_fragment(acc[i][j], 0.f);

    for (int k0 = 0; k0 < K; k0 += BK) {
        // ---- Load A tile (BM x BK = 128x32), convert to fp16 if needed ----
#pragma unroll
        for (int p = 0; p < 2; p++) {
            const int idx = tid + p * 512;       // 0..1023
            const int r  = idx >> 3;             // 0..127
            const int cg = (idx & 7) * 4;        // 0,4,...,28
            const int gr = rowBase + r;
            if constexpr (sizeof(TA) == 4) {
                float4 v = make_float4(0.f, 0.f, 0.f, 0.f);
                if (gr < M) v = *(const float4*)((const float*)A + (size_t)gr * K + k0 + cg);
                __half2 h0 = __float22half2_rn(make_float2(v.x, v.y));
                __half2 h1 = __float22half2_rn(make_float2(v.z, v.w));
                *(__half2*)&As[r][cg]     = h0;
                *(__half2*)&As[r][cg + 2] = h1;
            } else {
                uint2 v = make_uint2(0u, 0u);
                if (gr < M) v = *(const uint2*)((const __half*)A + (size_t)gr * K + k0 + cg);
                *(uint2*)&As[r][cg] = v;
            }
        }
        // ---- Load B tile (BK x BN = 32x256) fp16, raw uint4 copy ----
#pragma unroll
        for (int p = 0; p < 2; p++) {
            const int idx = tid + p * 512;       // 0..1023
            const int r  = idx >> 5;             // 0..31
            const int cg = (idx & 31) * 8;       // 0..248, 8 halves each
            uint4 v = *(const uint4*)(B + (size_t)(k0 + r) * N + cg);
            *(uint4*)&Bs[r][cg] = v;
        }
        __syncthreads();

#pragma unroll
        for (int kk = 0; kk < BK; kk += 16) {
            wmma::fragment<wmma::matrix_a, 16, 16, 16, __half, wmma::row_major> af[2];
            wmma::fragment<wmma::matrix_b, 16, 16, 16, __half, wmma::row_major> bf[4];
#pragma unroll
            for (int i = 0; i < 2; i++)
                wmma::load_matrix_sync(af[i], &As[warpM * 32 + i * 16][kk], BK + APAD);
#pragma unroll
            for (int j = 0; j < 4; j++)
                wmma::load_matrix_sync(bf[j], &Bs[kk][warpN * 64 + j * 16], BN + BPAD);
#pragma unroll
            for (int i = 0; i < 2; i++)
#pragma unroll
                for (int j = 0; j < 4; j++)
                    wmma::mma_sync(acc[i][j], af[i], bf[j], acc[i][j]);
        }
        __syncthreads();
    }

    // ---- Epilogue: fp32 acc -> fp16 C via per-warp smem staging ----
    float* st = &stage[wid][0];
    const int lr = lane >> 1;            // 0..15
    const int lc = (lane & 1) * 8;       // 0 or 8
#pragma unroll
    for (int i = 0; i < 2; i++) {
#pragma unroll
        for (int j = 0; j < 4; j++) {
            wmma::store_matrix_sync(st, acc[i][j], 16, wmma::mem_row_major);
            __syncwarp();
            const int gr = rowBase + warpM * 32 + i * 16 + lr;
            if (gr < M) {
                const float* src = st + lr * 16 + lc;
                __half2 h0 = __float22half2_rn(make_float2(src[0], src[1]));
                __half2 h1 = __float22half2_rn(make_float2(src[2], src[3]));
                __half2 h2 = __float22half2_rn(make_float2(src[4], src[5]));
                __half2 h3 = __float22half2_rn(make_float2(src[6], src[7]));
                uint4 packed;
                packed.x = *(unsigned*)&h0; packed.y = *(unsigned*)&h1;
                packed.z = *(unsigned*)&h2; packed.w = *(unsigned*)&h3;
                const int gc = warpN * 64 + j * 16 + lc;
                *(uint4*)(C + (size_t)gr * N + gc) = packed;
            }
            __syncwarp();
        }
    }
}

// ---------------------------------------------------------------------------
// CSR build
// ---------------------------------------------------------------------------
__global__ void histogram_kernel(const int* __restrict__ rows, int* __restrict__ counts, int E)
{
    for (int e = blockIdx.x * blockDim.x + threadIdx.x; e < E; e += gridDim.x * blockDim.x)
        atomicAdd(&counts[rows[e]], 1);
}

__global__ void scan1_kernel(const int* __restrict__ counts, int* __restrict__ rowPtr,
                             int* __restrict__ blockSums, int n)
{
    __shared__ int sh[SCAN_B];
    const int i = blockIdx.x * SCAN_B + threadIdx.x;
    int v = (i < n) ? counts[i] : 0;
    sh[threadIdx.x] = v;
    __syncthreads();
#pragma unroll
    for (int off = 1; off < SCAN_B; off <<= 1) {
        int t = (threadIdx.x >= off) ? sh[threadIdx.x - off] : 0;
        __syncthreads();
        sh[threadIdx.x] += t;
        __syncthreads();
    }
    if (i < n) rowPtr[i] = sh[threadIdx.x] - v;      // exclusive
    if (threadIdx.x == SCAN_B - 1) blockSums[blockIdx.x] = sh[SCAN_B - 1];
}

__global__ void scan2_kernel(int* __restrict__ blockSums, int nb)
{
    __shared__ int sh[512];
    int v = (threadIdx.x < nb) ? blockSums[threadIdx.x] : 0;
    sh[threadIdx.x] = v;
    __syncthreads();
#pragma unroll
    for (int off = 1; off < 512; off <<= 1) {
        int t = (threadIdx.x >= off) ? sh[threadIdx.x - off] : 0;
        __syncthreads();
        sh[threadIdx.x] += t;
        __syncthreads();
    }
    if (threadIdx.x < nb) blockSums[threadIdx.x] = sh[threadIdx.x] - v;  // exclusive
}

__global__ void scan3_kernel(int* __restrict__ rowPtr, const int* __restrict__ blockSums,
                             int* __restrict__ wptr, int n, int total)
{
    const int i = blockIdx.x * SCAN_B + threadIdx.x;
    if (i < n) {
        const int p = rowPtr[i] + blockSums[blockIdx.x];
        rowPtr[i] = p;
        wptr[i]   = p;
    }
    if (i == 0) rowPtr[n] = total;
}

// Pack (col, val) into one uint32: fp16 val bits (sign always 0 for val in
// [0,1)) in bits [31:17], col (< 2^17) in bits [16:0].
__global__ void scatter_kernel(const int* __restrict__ rows, const int* __restrict__ cols,
                               const float* __restrict__ vals, int* __restrict__ wptr,
                               unsigned* __restrict__ csr, int E)
{
    for (int e = blockIdx.x * blockDim.x + threadIdx.x; e < E; e += gridDim.x * blockDim.x) {
        const int r = rows[e];
        const int pos = atomicAdd(&wptr[r], 1);
        const unsigned hb = (unsigned)__half_as_ushort(__float2half(vals[e]));
        csr[pos] = (hb << 17) | (unsigned)cols[e];
    }
}

// ---------------------------------------------------------------------------
// Row gather: 4-edge batches, software-pipelined — the NEXT batch's csr quad
// is loaded while the CURRENT batch's row gathers are in flight, collapsing
// two serial L2 round-trips per batch into ~one.
// ---------------------------------------------------------------------------
__device__ __forceinline__ void unpack_edge(unsigned p, int& c, float& v)
{
    c = (int)(p & 0x1FFFFu);
    v = __half2float(__ushort_as_half((unsigned short)(p >> 17)));
}

__device__ __forceinline__ void edge_fma(
    const float4* __restrict__ S4, unsigned p, int lane, float acc[8])
{
    int c; float v;
    unpack_edge(p, c, v);
    const float4 raw = __ldg(&S4[(size_t)c * (HID / 8) + lane]);
    const __half2* h2 = (const __half2*)&raw;
#pragma unroll
    for (int q = 0; q < 4; q++) {
        float2 f = __half22float2(h2[q]);
        acc[q * 2 + 0] = fmaf(v, f.x, acc[q * 2 + 0]);
        acc[q * 2 + 1] = fmaf(v, f.y, acc[q * 2 + 1]);
    }
}

__device__ __forceinline__ void gather_row(
    const unsigned* __restrict__ csr, const float4* __restrict__ S4,
    int s, int e, int lane, float acc[8])
{
    int i = s;
    if (i + 3 < e) {
        // Prologue: load first csr quad.
        unsigned p[4];
#pragma unroll
        for (int u = 0; u < 4; u++) p[u] = __ldg(&csr[i + u]);

        for (; i + 3 < e; ) {
            // Issue gathers for current batch.
            int   c[4];
            float v[4];
#pragma unroll
            for (int u = 0; u < 4; u++) unpack_edge(p[u], c[u], v[u]);
            float4 r[4];
#pragma unroll
            for (int u = 0; u < 4; u++)
                r[u] = __ldg(&S4[(size_t)c[u] * (HID / 8) + lane]);

            // Prefetch next csr quad while gathers are in flight.
            i += 4;
            const bool more = (i + 3 < e);
            if (more) {
#pragma unroll
                for (int u = 0; u < 4; u++) p[u] = __ldg(&csr[i + u]);
            }

            // Consume current gathers.
#pragma unroll
            for (int u = 0; u < 4; u++) {
                const __half2* h2 = (const __half2*)&r[u];
#pragma unroll
                for (int q = 0; q < 4; q++) {
                    float2 f = __half22float2(h2[q]);
                    acc[q * 2 + 0] = fmaf(v[u], f.x, acc[q * 2 + 0]);
                    acc[q * 2 + 1] = fmaf(v[u], f.y, acc[q * 2 + 1]);
                }
            }
            if (!more) break;
        }
    }
    for (; i < e; i++)
        edge_fma(S4, __ldg(&csr[i]), lane, acc);
}

// ---------------------------------------------------------------------------
// SpMM: CSR gather from fp16 source, fused bias (+optional relu), fp16 out.
// One warp per destination node; lane owns cols [lane*8, lane*8+8).
// ---------------------------------------------------------------------------
template <bool RELU>
__global__ __launch_bounds__(256) void spmm_kernel(
    const int* __restrict__ rowPtr, const unsigned* __restrict__ csr,
    const __half* __restrict__ S, const float* __restrict__ bias,
    __half* __restrict__ Hout, int N)
{
    const int warp = (blockIdx.x * blockDim.x + threadIdx.x) >> 5;
    const int lane = threadIdx.x & 31;
    if (warp >= N) return;

    const int s = rowPtr[warp];
    const int e = rowPtr[warp + 1];

    float acc[8];
#pragma unroll
    for (int j = 0; j < 8; j++) acc[j] = 0.f;

    const float4* __restrict__ S4 = (const float4*)S;
    gather_row(csr, S4, s, e, lane, acc);

    const float4* __restrict__ b4 = (const float4*)bias;
    const float4 bb0 = __ldg(&b4[lane * 2 + 0]);
    const float4 bb1 = __ldg(&b4[lane * 2 + 1]);
#pragma unroll
    for (int q = 0; q < 4; q++) {
        acc[q]     += ((const float*)&bb0)[q];
        acc[q + 4] += ((const float*)&bb1)[q];
    }
    if (RELU) {
#pragma unroll
        for (int j = 0; j < 8; j++) acc[j] = fmaxf(acc[j], 0.f);
    }

    __half2 h0 = __float22half2_rn(make_float2(acc[0], acc[1]));
    __half2 h1 = __float22half2_rn(make_float2(acc[2], acc[3]));
    __half2 h2 = __float22half2_rn(make_float2(acc[4], acc[5]));
    __half2 h3 = __float22half2_rn(make_float2(acc[6], acc[7]));
    uint4 packed;
    packed.x = *(unsigned*)&h0; packed.y = *(unsigned*)&h1;
    packed.z = *(unsigned*)&h2; packed.w = *(unsigned*)&h3;
    *((uint4*)(Hout + (size_t)warp * HID) + lane) = packed;
}

// ---------------------------------------------------------------------------
// Tensor-core head: a = relu(L @ fc1W + fc1b); z = a @ fc2W + fc2b;
// out = log_softmax(z). 64 nodes/block, 128 threads = 4 warps.
// ---------------------------------------------------------------------------
__global__ __launch_bounds__(128) void head_wmma_kernel(
    const __half* __restrict__ L,
    const float* __restrict__ fc1W, const float* __restrict__ fc1b,
    const float* __restrict__ fc2W, const float* __restrict__ fc2b,
    float* __restrict__ out, int N)
{
    __shared__ __half Bw[HID][40];          // fc1W fp16, padded stride
    __shared__ float  stage[4][16 * 36];    // per-warp fp32 staging, ldm 36

    const int tid = threadIdx.x;
    for (int i = tid; i < HID * 32; i += blockDim.x) {
        const int r = i >> 5;
        const int c = i & 31;
        Bw[r][c] = __float2half(fc1W[i]);
    }
    __syncthreads();

    const int w = tid >> 5;
    const int lane = tid & 31;
    const int rowBase = blockIdx.x * 64 + w * 16;

    wmma::fragment<wmma::accumulator, 16, 16, 16, float> acc0, acc1;
    wmma::fill_fragment(acc0, 0.f);
    wmma::fill_fragment(acc1, 0.f);

    const __half* Abase = L + (size_t)rowBase * HID;
#pragma unroll
    for (int kk = 0; kk < HID; kk += 16) {
        wmma::fragment<wmma::matrix_a, 16, 16, 16, __half, wmma::row_major> af;
        wmma::fragment<wmma::matrix_b, 16, 16, 16, __half, wmma::row_major> bf0, bf1;
        wmma::load_matrix_sync(af, Abase + kk, HID);
        wmma::load_matrix_sync(bf0, &Bw[kk][0], 40);
        wmma::load_matrix_sync(bf1, &Bw[kk][16], 40);
        wmma::mma_sync(acc0, af, bf0, acc0);
        wmma::mma_sync(acc1, af, bf1, acc1);
    }

    float* st = &stage[w][0];
    wmma::store_matrix_sync(st,      acc0, 36, wmma::mem_row_major);
    wmma::store_matrix_sync(st + 16, acc1, 36, wmma::mem_row_major);
    __syncwarp();

    const float b1a = __ldg(&fc1b[lane]);
    const float w2a = __ldg(&fc2W[lane * 2 + 0]);
    const float w2b = __ldg(&fc2W[lane * 2 + 1]);
    const float zb0 = __ldg(&fc2b[0]);
    const float zb1 = __ldg(&fc2b[1]);

#pragma unroll 4
    for (int r = 0; r < 16; r++) {
        const int node = rowBase + r;
        float a = fmaxf(st[r * 36 + lane] + b1a, 0.f);
        float t0 = a * w2a;
        float t1 = a * w2b;
#pragma unroll
        for (int off = 16; off > 0; off >>= 1) {
            t0 += __shfl_down_sync(0xffffffffu, t0, off);
            t1 += __shfl_down_sync(0xffffffffu, t1, off);
        }
        if (lane == 0 && node < N) {
            const float z0 = t0 + zb0;
            const float z1 = t1 + zb1;
            const float m = fmaxf(z0, z1);
            const float lse = m + logf(expf(z0 - m) + expf(z1 - m));
            out[node * 2 + 0] = z0 - lse;
            out[node * 2 + 1] = z1 - lse;
        }
    }
}

// ---------------------------------------------------------------------------
extern "C" void kernel_launch(void* const* d_in, const int* in_sizes, int n_in,
                              void* d_out, int out_size)
{
    const float* inputs    = (const float*)d_in[0];
    const int*   edge_rows = (const int*)  d_in[1];
    const int*   edge_cols = (const int*)  d_in[2];
    const float* edge_vals = (const float*)d_in[3];
    const float* W1        = (const float*)d_in[4];
    const float* b1        = (const float*)d_in[5];
    const float* W2        = (const float*)d_in[6];
    const float* b2        = (const float*)d_in[7];
    const float* fc1W      = (const float*)d_in[8];
    const float* fc1b      = (const float*)d_in[9];
    const float* fc2W      = (const float*)d_in[10];
    const float* fc2b      = (const float*)d_in[11];
    float* out = (float*)d_out;

    const int N = in_sizes[0] / IN_DIM;   // 100000
    const int E = in_sizes[1];            // 3200000

    __half* bufS; __half* bufH; __half* W1h; __half* W2h;
    int* counts; int* rowPtr; int* blockSums; unsigned* csr;
    cudaGetSymbolAddress((void**)&bufS, g_bufS);
    cudaGetSymbolAddress((void**)&bufH, g_bufH);
    cudaGetSymbolAddress((void**)&W1h, g_W1h);
    cudaGetSymbolAddress((void**)&W2h, g_W2h);
    cudaGetSymbolAddress((void**)&counts, g_counts);
    cudaGetSymbolAddress((void**)&rowPtr, g_rowPtr);
    cudaGetSymbolAddress((void**)&blockSums, g_blockSums);
    cudaGetSymbolAddress((void**)&csr, g_csr);

    const int nScanBlocks = (N + SCAN_B - 1) / SCAN_B;   // 391

    // One-time creation of side stream + fork/join events (host objects only).
    static cudaStream_t s_side = nullptr;
    static cudaEvent_t  s_evFork = nullptr, s_evJoin = nullptr;
    if (s_side == nullptr) {
        cudaStreamCreateWithFlags(&s_side, cudaStreamNonBlocking);
        cudaEventCreateWithFlags(&s_evFork, cudaEventDisableTiming);
        cudaEventCreateWithFlags(&s_evJoin, cudaEventDisableTiming);
    }

    // ---- Fork: CSR build on side stream, weight convert + GEMM1 on main ----
    cudaEventRecord(s_evFork, 0);
    cudaStreamWaitEvent(s_side, s_evFork, 0);

    cudaMemsetAsync(counts, 0, (size_t)N * sizeof(int), s_side);
    histogram_kernel<<<512, 256, 0, s_side>>>(edge_rows, counts, E);
    scan1_kernel<<<nScanBlocks, SCAN_B, 0, s_side>>>(counts, rowPtr, blockSums, N);
    scan2_kernel<<<1, 512, 0, s_side>>>(blockSums, nScanBlocks);
    scan3_kernel<<<nScanBlocks, SCAN_B, 0, s_side>>>(rowPtr, blockSums, counts /*wptr*/, N, E);
    scatter_kernel<<<512, 256, 0, s_side>>>(edge_rows, edge_cols, edge_vals, counts, csr, E);
    cudaEventRecord(s_evJoin, s_side);

    const int gemmBlocks = (N + BM - 1) / BM;   // 782 (BN == HID)
    const int spmmBlocks = (N + 7) / 8;         // 8 warps/block, warp per node

    // ---- Weight conversion, then Layer 1: S1 = f16(X @ W1h) ----
    convert_w_kernel<<<(IN_DIM * HID + 255) / 256, 256>>>(W1, W2, W1h, W2h);
    gemm_tc_kernel<float><<<gemmBlocks, 512>>>(inputs, W1h, bufS, N, IN_DIM, HID);

    // ---- Join: SpMM needs both S1 and the CSR ----
    cudaStreamWaitEvent(0, s_evJoin, 0);

    // H = f16(relu(spmm(S1) + b1))
    spmm_kernel<true><<<spmmBlocks, 256>>>(rowPtr, csr, bufS, b1, bufH, N);

    // ---- Layer 2: S2 = f16(H @ W2h); L = f16(spmm(S2) + b2) ----
    gemm_tc_kernel<__half><<<gemmBlocks, 512>>>(bufH, W2h, bufS, N, HID, HID);
    spmm_kernel<false><<<spmmBlocks, 256>>>(rowPtr, csr, bufS, b2, bufH, N);

    // ---- Tensor-core head + log_softmax ----
    head_wmma_kernel<<<(N + 63) / 64, 128>>>(bufH, fc1W, fc1b, fc2W, fc2b, out, N);
}

// round 16
// speedup vs baseline: 1.0163x; 1.0163x over previous
#include <cuda_runtime.h>
#include <cuda_fp16.h>
#include <mma.h>
#include <math.h>

using namespace nvcuda;

#define N_NODES_MAX 100000
#define E_MAX 3200000
#define IN_DIM 512
#define HID 256
#define SCAN_B 256

// GEMM tiles: full-width N so A is read exactly once; BM=128 halves B-traffic.
#define BM 128
#define BN 256
#define BK 32
#define APAD 8
#define BPAD 8

// Static device scratch (allocation-free). bufH padded by 64 rows so the
// head kernel's last block can issue full wmma tile loads safely.
__device__ __half g_bufS[(size_t)N_NODES_MAX * HID];          // fp16 support S
__device__ __half g_bufH[(size_t)(N_NODES_MAX + 64) * HID];   // fp16 H, then L
__device__ __half g_W1h[IN_DIM * HID];                        // fp16 W1
__device__ __half g_W2h[HID * HID];                           // fp16 W2
__device__ int    g_counts[N_NODES_MAX];
__device__ int    g_rowPtr[N_NODES_MAX + 1];
__device__ int    g_blockSums[(N_NODES_MAX + SCAN_B - 1) / SCAN_B + 1];
__device__ unsigned g_csr[E_MAX];   // packed edge: val_fp16_bits[14:0] << 17 | col[16:0]

// ---------------------------------------------------------------------------
// One-shot fp32 -> fp16 weight conversion (W1 then W2).
// ---------------------------------------------------------------------------
__global__ void convert_w_kernel(const float* __restrict__ W1,
                                 const float* __restrict__ W2,
                                 __half* __restrict__ W1h,
                                 __half* __restrict__ W2h)
{
    const int i = blockIdx.x * blockDim.x + threadIdx.x;
    if (i < IN_DIM * HID) W1h[i] = __float2half(W1[i]);
    if (i < HID * HID)    W2h[i] = __float2half(W2[i]);
}

// ---------------------------------------------------------------------------
// Tensor-core GEMM: C[M,N] = half(A[M,K] @ B[K,N]); A fp32 or fp16 (converted
// in the loader), B fp16 (pre-converted weights), fp32 accumulate, fp16 out.
// BM=128, BN=256, BK=32, 512 threads = 16 warps (4 along M x 4 along N).
// ---------------------------------------------------------------------------
template <typename TA>
__global__ __launch_bounds__(512) void gemm_tc_kernel(
    const TA* __restrict__ A, const __half* __restrict__ B,
    __half* __restrict__ C, int M, int K, int N)
{
    __shared__ __half As[BM][BK + APAD];
    __shared__ __half Bs[BK][BN + BPAD];
    __shared__ float  stage[16][16 * 16];

    const int tid = threadIdx.x;
    const int wid = tid >> 5;
    const int lane = tid & 31;
    const int warpM = wid & 3;          // 0..3 -> 32 rows each
    const int warpN = wid >> 2;         // 0..3 -> 64 cols each
    const int rowBase = blockIdx.x * BM;

    wmma::fragment<wmma::accumulator, 16, 16, 16, float> acc[2][4];
#pragma unroll
    for (int i = 0; i < 2; i++)
#pragma unroll
        for (int j = 0; j < 4; j++) wmma::fill_fragment(acc[i][j], 0.f);

    for (int k0 = 0; k0 < K; k0 += BK) {
        // ---- Load A tile (BM x BK = 128x32), convert to fp16 if needed ----
#pragma unroll
        for (int p = 0; p < 2; p++) {
            const int idx = tid + p * 512;       // 0..1023
            const int r  = idx >> 3;             // 0..127
            const int cg = (idx & 7) * 4;        // 0,4,...,28
            const int gr = rowBase + r;
            if constexpr (sizeof(TA) == 4) {
                float4 v = make_float4(0.f, 0.f, 0.f, 0.f);
                if (gr < M) v = *(const float4*)((const float*)A + (size_t)gr * K + k0 + cg);
                __half2 h0 = __float22half2_rn(make_float2(v.x, v.y));
                __half2 h1 = __float22half2_rn(make_float2(v.z, v.w));
                *(__half2*)&As[r][cg]     = h0;
                *(__half2*)&As[r][cg + 2] = h1;
            } else {
                uint2 v = make_uint2(0u, 0u);
                if (gr < M) v = *(const uint2*)((const __half*)A + (size_t)gr * K + k0 + cg);
                *(uint2*)&As[r][cg] = v;
            }
        }
        // ---- Load B tile (BK x BN = 32x256) fp16, raw uint4 copy ----
#pragma unroll
        for (int p = 0; p < 2; p++) {
            const int idx = tid + p * 512;       // 0..1023
            const int r  = idx >> 5;             // 0..31
            const int cg = (idx & 31) * 8;       // 0..248, 8 halves each
            uint4 v = *(const uint4*)(B + (size_t)(k0 + r) * N + cg);
            *(uint4*)&Bs[r][cg] = v;
        }
        __syncthreads();

#pragma unroll
        for (int kk = 0; kk < BK; kk += 16) {
            wmma::fragment<wmma::matrix_a, 16, 16, 16, __half, wmma::row_major> af[2];
            wmma::fragment<wmma::matrix_b, 16, 16, 16, __half, wmma::row_major> bf[4];
#pragma unroll
            for (int i = 0; i < 2; i++)
                wmma::load_matrix_sync(af[i], &As[warpM * 32 + i * 16][kk], BK + APAD);
#pragma unroll
            for (int j = 0; j < 4; j++)
                wmma::load_matrix_sync(bf[j], &Bs[kk][warpN * 64 + j * 16], BN + BPAD);
#pragma unroll
            for (int i = 0; i < 2; i++)
#pragma unroll
                for (int j = 0; j < 4; j++)
                    wmma::mma_sync(acc[i][j], af[i], bf[j], acc[i][j]);
        }
        __syncthreads();
    }

    // ---- Epilogue: fp32 acc -> fp16 C via per-warp smem staging ----
    float* st = &stage[wid][0];
    const int lr = lane >> 1;            // 0..15
    const int lc = (lane & 1) * 8;       // 0 or 8
#pragma unroll
    for (int i = 0; i < 2; i++) {
#pragma unroll
        for (int j = 0; j < 4; j++) {
            wmma::store_matrix_sync(st, acc[i][j], 16, wmma::mem_row_major);
            __syncwarp();
            const int gr = rowBase + warpM * 32 + i * 16 + lr;
            if (gr < M) {
                const float* src = st + lr * 16 + lc;
                __half2 h0 = __float22half2_rn(make_float2(src[0], src[1]));
                __half2 h1 = __float22half2_rn(make_float2(src[2], src[3]));
                __half2 h2 = __float22half2_rn(make_float2(src[4], src[5]));
                __half2 h3 = __float22half2_rn(make_float2(src[6], src[7]));
                uint4 packed;
                packed.x = *(unsigned*)&h0; packed.y = *(unsigned*)&h1;
                packed.z = *(unsigned*)&h2; packed.w = *(unsigned*)&h3;
                const int gc = warpN * 64 + j * 16 + lc;
                *(uint4*)(C + (size_t)gr * N + gc) = packed;
            }
            __syncwarp();
        }
    }
}

// ---------------------------------------------------------------------------
// CSR build
// ---------------------------------------------------------------------------
__global__ void histogram_kernel(const int* __restrict__ rows, int* __restrict__ counts, int E)
{
    for (int e = blockIdx.x * blockDim.x + threadIdx.x; e < E; e += gridDim.x * blockDim.x)
        atomicAdd(&counts[rows[e]], 1);
}

__global__ void scan1_kernel(const int* __restrict__ counts, int* __restrict__ rowPtr,
                             int* __restrict__ blockSums, int n)
{
    __shared__ int sh[SCAN_B];
    const int i = blockIdx.x * SCAN_B + threadIdx.x;
    int v = (i < n) ? counts[i] : 0;
    sh[threadIdx.x] = v;
    __syncthreads();
#pragma unroll
    for (int off = 1; off < SCAN_B; off <<= 1) {
        int t = (threadIdx.x >= off) ? sh[threadIdx.x - off] : 0;
        __syncthreads();
        sh[threadIdx.x] += t;
        __syncthreads();
    }
    if (i < n) rowPtr[i] = sh[threadIdx.x] - v;      // exclusive
    if (threadIdx.x == SCAN_B - 1) blockSums[blockIdx.x] = sh[SCAN_B - 1];
}

__global__ void scan2_kernel(int* __restrict__ blockSums, int nb)
{
    __shared__ int sh[512];
    int v = (threadIdx.x < nb) ? blockSums[threadIdx.x] : 0;
    sh[threadIdx.x] = v;
    __syncthreads();
#pragma unroll
    for (int off = 1; off < 512; off <<= 1) {
        int t = (threadIdx.x >= off) ? sh[threadIdx.x - off] : 0;
        __syncthreads();
        sh[threadIdx.x] += t;
        __syncthreads();
    }
    if (threadIdx.x < nb) blockSums[threadIdx.x] = sh[threadIdx.x] - v;  // exclusive
}

__global__ void scan3_kernel(int* __restrict__ rowPtr, const int* __restrict__ blockSums,
                             int* __restrict__ wptr, int n, int total)
{
    const int i = blockIdx.x * SCAN_B + threadIdx.x;
    if (i < n) {
        const int p = rowPtr[i] + blockSums[blockIdx.x];
        rowPtr[i] = p;
        wptr[i]   = p;
    }
    if (i == 0) rowPtr[n] = total;
}

// Pack (col, val) into one uint32: fp16 val bits (sign always 0 for val in
// [0,1)) in bits [31:17], col (< 2^17) in bits [16:0].
__global__ void scatter_kernel(const int* __restrict__ rows, const int* __restrict__ cols,
                               const float* __restrict__ vals, int* __restrict__ wptr,
                               unsigned* __restrict__ csr, int E)
{
    for (int e = blockIdx.x * blockDim.x + threadIdx.x; e < E; e += gridDim.x * blockDim.x) {
        const int r = rows[e];
        const int pos = atomicAdd(&wptr[r], 1);
        const unsigned hb = (unsigned)__half_as_ushort(__float2half(vals[e]));
        csr[pos] = (hb << 17) | (unsigned)cols[e];
    }
}

// ---------------------------------------------------------------------------
// Row gather: plain 4-edge unrolled batches (R13-proven best).
// ---------------------------------------------------------------------------
__device__ __forceinline__ void unpack_edge(unsigned p, int& c, float& v)
{
    c = (int)(p & 0x1FFFFu);
    v = __half2float(__ushort_as_half((unsigned short)(p >> 17)));
}

__device__ __forceinline__ void edge_fma(
    const float4* __restrict__ S4, unsigned p, int lane, float acc[8])
{
    int c; float v;
    unpack_edge(p, c, v);
    const float4 raw = __ldg(&S4[(size_t)c * (HID / 8) + lane]);
    const __half2* h2 = (const __half2*)&raw;
#pragma unroll
    for (int q = 0; q < 4; q++) {
        float2 f = __half22float2(h2[q]);
        acc[q * 2 + 0] = fmaf(v, f.x, acc[q * 2 + 0]);
        acc[q * 2 + 1] = fmaf(v, f.y, acc[q * 2 + 1]);
    }
}

__device__ __forceinline__ void gather_row(
    const unsigned* __restrict__ csr, const float4* __restrict__ S4,
    int s, int e, int lane, float acc[8])
{
    int i = s;
    for (; i + 3 < e; i += 4) {
        unsigned p[4];
#pragma unroll
        for (int u = 0; u < 4; u++) p[u] = __ldg(&csr[i + u]);
        int   c[4];
        float v[4];
#pragma unroll
        for (int u = 0; u < 4; u++) unpack_edge(p[u], c[u], v[u]);
        float4 r[4];
#pragma unroll
        for (int u = 0; u < 4; u++)
            r[u] = __ldg(&S4[(size_t)c[u] * (HID / 8) + lane]);
#pragma unroll
        for (int u = 0; u < 4; u++) {
            const __half2* h2 = (const __half2*)&r[u];
#pragma unroll
            for (int q = 0; q < 4; q++) {
                float2 f = __half22float2(h2[q]);
                acc[q * 2 + 0] = fmaf(v[u], f.x, acc[q * 2 + 0]);
                acc[q * 2 + 1] = fmaf(v[u], f.y, acc[q * 2 + 1]);
            }
        }
    }
    for (; i < e; i++)
        edge_fma(S4, __ldg(&csr[i]), lane, acc);
}

// ---------------------------------------------------------------------------
// SpMM: CSR gather from fp16 source, fused bias (+optional relu), fp16 out.
// One warp per destination node in [base, base+count); lane owns 8 cols.
// ---------------------------------------------------------------------------
template <bool RELU>
__global__ __launch_bounds__(256) void spmm_kernel(
    const int* __restrict__ rowPtr, const unsigned* __restrict__ csr,
    const __half* __restrict__ S, const float* __restrict__ bias,
    __half* __restrict__ Hout, int base, int count)
{
    const int w = (blockIdx.x * blockDim.x + threadIdx.x) >> 5;
    const int lane = threadIdx.x & 31;
    if (w >= count) return;
    const int node = base + w;

    const int s = rowPtr[node];
    const int e = rowPtr[node + 1];

    float acc[8];
#pragma unroll
    for (int j = 0; j < 8; j++) acc[j] = 0.f;

    const float4* __restrict__ S4 = (const float4*)S;
    gather_row(csr, S4, s, e, lane, acc);

    const float4* __restrict__ b4 = (const float4*)bias;
    const float4 bb0 = __ldg(&b4[lane * 2 + 0]);
    const float4 bb1 = __ldg(&b4[lane * 2 + 1]);
#pragma unroll
    for (int q = 0; q < 4; q++) {
        acc[q]     += ((const float*)&bb0)[q];
        acc[q + 4] += ((const float*)&bb1)[q];
    }
    if (RELU) {
#pragma unroll
        for (int j = 0; j < 8; j++) acc[j] = fmaxf(acc[j], 0.f);
    }

    __half2 h0 = __float22half2_rn(make_float2(acc[0], acc[1]));
    __half2 h1 = __float22half2_rn(make_float2(acc[2], acc[3]));
    __half2 h2 = __float22half2_rn(make_float2(acc[4], acc[5]));
    __half2 h3 = __float22half2_rn(make_float2(acc[6], acc[7]));
    uint4 packed;
    packed.x = *(unsigned*)&h0; packed.y = *(unsigned*)&h1;
    packed.z = *(unsigned*)&h2; packed.w = *(unsigned*)&h3;
    *((uint4*)(Hout + (size_t)node * HID) + lane) = packed;
}

// ---------------------------------------------------------------------------
// Tensor-core head: a = relu(L @ fc1W + fc1b); z = a @ fc2W + fc2b;
// out = log_softmax(z). 64 nodes/block, 128 threads = 4 warps.
// ---------------------------------------------------------------------------
__global__ __launch_bounds__(128) void head_wmma_kernel(
    const __half* __restrict__ L,
    const float* __restrict__ fc1W, const float* __restrict__ fc1b,
    const float* __restrict__ fc2W, const float* __restrict__ fc2b,
    float* __restrict__ out, int N)
{
    __shared__ __half Bw[HID][40];          // fc1W fp16, padded stride
    __shared__ float  stage[4][16 * 36];    // per-warp fp32 staging, ldm 36

    const int tid = threadIdx.x;
    for (int i = tid; i < HID * 32; i += blockDim.x) {
        const int r = i >> 5;
        const int c = i & 31;
        Bw[r][c] = __float2half(fc1W[i]);
    }
    __syncthreads();

    const int w = tid >> 5;
    const int lane = tid & 31;
    const int rowBase = blockIdx.x * 64 + w * 16;

    wmma::fragment<wmma::accumulator, 16, 16, 16, float> acc0, acc1;
    wmma::fill_fragment(acc0, 0.f);
    wmma::fill_fragment(acc1, 0.f);

    const __half* Abase = L + (size_t)rowBase * HID;
#pragma unroll
    for (int kk = 0; kk < HID; kk += 16) {
        wmma::fragment<wmma::matrix_a, 16, 16, 16, __half, wmma::row_major> af;
        wmma::fragment<wmma::matrix_b, 16, 16, 16, __half, wmma::row_major> bf0, bf1;
        wmma::load_matrix_sync(af, Abase + kk, HID);
        wmma::load_matrix_sync(bf0, &Bw[kk][0], 40);
        wmma::load_matrix_sync(bf1, &Bw[kk][16], 40);
        wmma::mma_sync(acc0, af, bf0, acc0);
        wmma::mma_sync(acc1, af, bf1, acc1);
    }

    float* st = &stage[w][0];
    wmma::store_matrix_sync(st,      acc0, 36, wmma::mem_row_major);
    wmma::store_matrix_sync(st + 16, acc1, 36, wmma::mem_row_major);
    __syncwarp();

    const float b1a = __ldg(&fc1b[lane]);
    const float w2a = __ldg(&fc2W[lane * 2 + 0]);
    const float w2b = __ldg(&fc2W[lane * 2 + 1]);
    const float zb0 = __ldg(&fc2b[0]);
    const float zb1 = __ldg(&fc2b[1]);

#pragma unroll 4
    for (int r = 0; r < 16; r++) {
        const int node = rowBase + r;
        float a = fmaxf(st[r * 36 + lane] + b1a, 0.f);
        float t0 = a * w2a;
        float t1 = a * w2b;
#pragma unroll
        for (int off = 16; off > 0; off >>= 1) {
            t0 += __shfl_down_sync(0xffffffffu, t0, off);
            t1 += __shfl_down_sync(0xffffffffu, t1, off);
        }
        if (lane == 0 && node < N) {
            const float z0 = t0 + zb0;
            const float z1 = t1 + zb1;
            const float m = fmaxf(z0, z1);
            const float lse = m + logf(expf(z0 - m) + expf(z1 - m));
            out[node * 2 + 0] = z0 - lse;
            out[node * 2 + 1] = z1 - lse;
        }
    }
}

// ---------------------------------------------------------------------------
extern "C" void kernel_launch(void* const* d_in, const int* in_sizes, int n_in,
                              void* d_out, int out_size)
{
    const float* inputs    = (const float*)d_in[0];
    const int*   edge_rows = (const int*)  d_in[1];
    const int*   edge_cols = (const int*)  d_in[2];
    const float* edge_vals = (const float*)d_in[3];
    const float* W1        = (const float*)d_in[4];
    const float* b1        = (const float*)d_in[5];
    const float* W2        = (const float*)d_in[6];
    const float* b2        = (const float*)d_in[7];
    const float* fc1W      = (const float*)d_in[8];
    const float* fc1b      = (const float*)d_in[9];
    const float* fc2W      = (const float*)d_in[10];
    const float* fc2b      = (const float*)d_in[11];
    float* out = (float*)d_out;

    const int N = in_sizes[0] / IN_DIM;   // 100000
    const int E = in_sizes[1];            // 3200000

    __half* bufS; __half* bufH; __half* W1h; __half* W2h;
    int* counts; int* rowPtr; int* blockSums; unsigned* csr;
    cudaGetSymbolAddress((void**)&bufS, g_bufS);
    cudaGetSymbolAddress((void**)&bufH, g_bufH);
    cudaGetSymbolAddress((void**)&W1h, g_W1h);
    cudaGetSymbolAddress((void**)&W2h, g_W2h);
    cudaGetSymbolAddress((void**)&counts, g_counts);
    cudaGetSymbolAddress((void**)&rowPtr, g_rowPtr);
    cudaGetSymbolAddress((void**)&blockSums, g_blockSums);
    cudaGetSymbolAddress((void**)&csr, g_csr);

    const int nScanBlocks = (N + SCAN_B - 1) / SCAN_B;   // 391

    // One-time creation of side stream + events (host objects only).
    static cudaStream_t s_side = nullptr;
    static cudaEvent_t  s_evFork = nullptr, s_evJoin = nullptr;
    static cudaEvent_t  s_evH1 = nullptr, s_evG2a = nullptr;
    if (s_side == nullptr) {
        cudaStreamCreateWithFlags(&s_side, cudaStreamNonBlocking);
        cudaEventCreateWithFlags(&s_evFork, cudaEventDisableTiming);
        cudaEventCreateWithFlags(&s_evJoin, cudaEventDisableTiming);
        cudaEventCreateWithFlags(&s_evH1, cudaEventDisableTiming);
        cudaEventCreateWithFlags(&s_evG2a, cudaEventDisableTiming);
    }

    // ---- Fork: CSR build on side stream, weight convert + GEMM1 on main ----
    cudaEventRecord(s_evFork, 0);
    cudaStreamWaitEvent(s_side, s_evFork, 0);

    cudaMemsetAsync(counts, 0, (size_t)N * sizeof(int), s_side);
    histogram_kernel<<<512, 256, 0, s_side>>>(edge_rows, counts, E);
    scan1_kernel<<<nScanBlocks, SCAN_B, 0, s_side>>>(counts, rowPtr, blockSums, N);
    scan2_kernel<<<1, 512, 0, s_side>>>(blockSums, nScanBlocks);
    scan3_kernel<<<nScanBlocks, SCAN_B, 0, s_side>>>(rowPtr, blockSums, counts /*wptr*/, N, E);
    scatter_kernel<<<512, 256, 0, s_side>>>(edge_rows, edge_cols, edge_vals, counts, csr, E);
    cudaEventRecord(s_evJoin, s_side);

    const int gemmBlocks = (N + BM - 1) / BM;       // full-matrix GEMM blocks
    // Node split for the spmm1 / gemm2 pipeline (multiple of BM)
    const int NA = ((N / 2) / BM) * BM;             // 49920
    const int NB = N - NA;

    // ---- Weight conversion, then Layer 1: S1 = f16(X @ W1h) ----
    convert_w_kernel<<<(IN_DIM * HID + 255) / 256, 256>>>(W1, W2, W1h, W2h);
    gemm_tc_kernel<float><<<gemmBlocks, 512>>>(inputs, W1h, bufS, N, IN_DIM, HID);

    // ---- Join: SpMM needs both S1 and the CSR ----
    cudaStreamWaitEvent(0, s_evJoin, 0);

    // ---- spmm1 split into halves; gemm2 first half overlaps spmm1 tail ----
    // spmm1a: nodes [0, NA)
    spmm_kernel<true><<<(NA + 7) / 8, 256>>>(rowPtr, csr, bufS, b1, bufH, 0, NA);
    cudaEventRecord(s_evH1, 0);
    // spmm1b: nodes [NA, N)
    spmm_kernel<true><<<(NB + 7) / 8, 256>>>(rowPtr, csr, bufS, b1, bufH, NA, NB);

    // side: gemm2a on H rows [0, NA) once spmm1a is done (concurrent w/ spmm1b)
    cudaStreamWaitEvent(s_side, s_evH1, 0);
    gemm_tc_kernel<__half><<<NA / BM, 512, 0, s_side>>>(bufH, W2h, bufS, NA, HID, HID);
    cudaEventRecord(s_evG2a, s_side);

    // main: gemm2b on H rows [NA, N)
    gemm_tc_kernel<__half><<<(NB + BM - 1) / BM, 512>>>(
        bufH + (size_t)NA * HID, W2h, bufS + (size_t)NA * HID, NB, HID, HID);

    // spmm2 needs ALL of S2: join gemm2a
    cudaStreamWaitEvent(0, s_evG2a, 0);
    spmm_kernel<false><<<(N + 7) / 8, 256>>>(rowPtr, csr, bufS, b2, bufH, 0, N);

    // ---- Tensor-core head + log_softmax ----
    head_wmma_kernel<<<(N + 63) / 64, 128>>>(bufH, fc1W, fc1b, fc2W, fc2b, out, N);
}

// round 17
// speedup vs baseline: 1.0199x; 1.0036x over previous
#include <cuda_runtime.h>
#include <cuda_fp16.h>
#include <mma.h>
#include <math.h>

using namespace nvcuda;

#define N_NODES_MAX 100000
#define E_MAX 3200000
#define IN_DIM 512
#define HID 256
#define SCAN_B 256

// GEMM tiles: full-width N so A is read exactly once; BM=128 halves B-traffic.
#define BM 128
#define BN 256
#define BK 32
#define APAD 8
#define BPAD 8

// Static device scratch (allocation-free). bufH padded by 64 rows so the
// head kernel's last block can issue full wmma tile loads safely.
__device__ __half g_bufS[(size_t)N_NODES_MAX * HID];          // fp16 support S
__device__ __half g_bufH[(size_t)(N_NODES_MAX + 64) * HID];   // fp16 H, then L
__device__ __half g_W1h[IN_DIM * HID];                        // fp16 W1
__device__ __half g_W2h[HID * HID];                           // fp16 W2
__device__ int    g_counts[N_NODES_MAX];
__device__ int    g_rowPtr[N_NODES_MAX + 1];
__device__ int    g_blockSums[(N_NODES_MAX + SCAN_B - 1) / SCAN_B + 1];
__device__ unsigned g_csr[E_MAX];   // packed edge: val_fp16_bits[14:0] << 17 | col[16:0]

// ---------------------------------------------------------------------------
// One-shot fp32 -> fp16 weight conversion (W1 then W2).
// ---------------------------------------------------------------------------
__global__ void convert_w_kernel(const float* __restrict__ W1,
                                 const float* __restrict__ W2,
                                 __half* __restrict__ W1h,
                                 __half* __restrict__ W2h)
{
    const int i = blockIdx.x * blockDim.x + threadIdx.x;
    if (i < IN_DIM * HID) W1h[i] = __float2half(W1[i]);
    if (i < HID * HID)    W2h[i] = __float2half(W2[i]);
}

// ---------------------------------------------------------------------------
// Tensor-core GEMM: C[M,N] = half(A[M,K] @ B[K,N]); A fp32 or fp16 (converted
// in the loader), B fp16 (pre-converted weights), fp32 accumulate, fp16 out.
// BM=128, BN=256, BK=32, 512 threads = 16 warps (4 along M x 4 along N).
// ---------------------------------------------------------------------------
template <typename TA>
__global__ __launch_bounds__(512) void gemm_tc_kernel(
    const TA* __restrict__ A, const __half* __restrict__ B,
    __half* __restrict__ C, int M, int K, int N)
{
    __shared__ __half As[BM][BK + APAD];
    __shared__ __half Bs[BK][BN + BPAD];
    __shared__ float  stage[16][16 * 16];

    const int tid = threadIdx.x;
    const int wid = tid >> 5;
    const int lane = tid & 31;
    const int warpM = wid & 3;          // 0..3 -> 32 rows each
    const int warpN = wid >> 2;         // 0..3 -> 64 cols each
    const int rowBase = blockIdx.x * BM;

    wmma::fragment<wmma::accumulator, 16, 16, 16, float> acc[2][4];
#pragma unroll
    for (int i = 0; i < 2; i++)
#pragma unroll
        for (int j = 0; j < 4; j++) wmma::fill_fragment(acc[i][j], 0.f);

    for (int k0 = 0; k0 < K; k0 += BK) {
        // ---- Load A tile (BM x BK = 128x32), convert to fp16 if needed ----
#pragma unroll
        for (int p = 0; p < 2; p++) {
            const int idx = tid + p * 512;       // 0..1023
            const int r  = idx >> 3;             // 0..127
            const int cg = (idx & 7) * 4;        // 0,4,...,28
            const int gr = rowBase + r;
            if constexpr (sizeof(TA) == 4) {
                float4 v = make_float4(0.f, 0.f, 0.f, 0.f);
                if (gr < M) v = *(const float4*)((const float*)A + (size_t)gr * K + k0 + cg);
                __half2 h0 = __float22half2_rn(make_float2(v.x, v.y));
                __half2 h1 = __float22half2_rn(make_float2(v.z, v.w));
                *(__half2*)&As[r][cg]     = h0;
                *(__half2*)&As[r][cg + 2] = h1;
            } else {
                uint2 v = make_uint2(0u, 0u);
                if (gr < M) v = *(const uint2*)((const __half*)A + (size_t)gr * K + k0 + cg);
                *(uint2*)&As[r][cg] = v;
            }
        }
        // ---- Load B tile (BK x BN = 32x256) fp16, raw uint4 copy ----
#pragma unroll
        for (int p = 0; p < 2; p++) {
            const int idx = tid + p * 512;       // 0..1023
            const int r  = idx >> 5;             // 0..31
            const int cg = (idx & 31) * 8;       // 0..248, 8 halves each
            uint4 v = *(const uint4*)(B + (size_t)(k0 + r) * N + cg);
            *(uint4*)&Bs[r][cg] = v;
        }
        __syncthreads();

#pragma unroll
        for (int kk = 0; kk < BK; kk += 16) {
            wmma::fragment<wmma::matrix_a, 16, 16, 16, __half, wmma::row_major> af[2];
            wmma::fragment<wmma::matrix_b, 16, 16, 16, __half, wmma::row_major> bf[4];
#pragma unroll
            for (int i = 0; i < 2; i++)
                wmma::load_matrix_sync(af[i], &As[warpM * 32 + i * 16][kk], BK + APAD);
#pragma unroll
            for (int j = 0; j < 4; j++)
                wmma::load_matrix_sync(bf[j], &Bs[kk][warpN * 64 + j * 16], BN + BPAD);
#pragma unroll
            for (int i = 0; i < 2; i++)
#pragma unroll
                for (int j = 0; j < 4; j++)
                    wmma::mma_sync(acc[i][j], af[i], bf[j], acc[i][j]);
        }
        __syncthreads();
    }

    // ---- Epilogue: fp32 acc -> fp16 C via per-warp smem staging ----
    float* st = &stage[wid][0];
    const int lr = lane >> 1;            // 0..15
    const int lc = (lane & 1) * 8;       // 0 or 8
#pragma unroll
    for (int i = 0; i < 2; i++) {
#pragma unroll
        for (int j = 0; j < 4; j++) {
            wmma::store_matrix_sync(st, acc[i][j], 16, wmma::mem_row_major);
            __syncwarp();
            const int gr = rowBase + warpM * 32 + i * 16 + lr;
            if (gr < M) {
                const float* src = st + lr * 16 + lc;
                __half2 h0 = __float22half2_rn(make_float2(src[0], src[1]));
                __half2 h1 = __float22half2_rn(make_float2(src[2], src[3]));
                __half2 h2 = __float22half2_rn(make_float2(src[4], src[5]));
                __half2 h3 = __float22half2_rn(make_float2(src[6], src[7]));
                uint4 packed;
                packed.x = *(unsigned*)&h0; packed.y = *(unsigned*)&h1;
                packed.z = *(unsigned*)&h2; packed.w = *(unsigned*)&h3;
                const int gc = warpN * 64 + j * 16 + lc;
                *(uint4*)(C + (size_t)gr * N + gc) = packed;
            }
            __syncwarp();
        }
    }
}

// ---------------------------------------------------------------------------
// CSR build
// ---------------------------------------------------------------------------
__global__ void histogram_kernel(const int* __restrict__ rows, int* __restrict__ counts, int E)
{
    for (int e = blockIdx.x * blockDim.x + threadIdx.x; e < E; e += gridDim.x * blockDim.x)
        atomicAdd(&counts[rows[e]], 1);
}

__global__ void scan1_kernel(const int* __restrict__ counts, int* __restrict__ rowPtr,
                             int* __restrict__ blockSums, int n)
{
    __shared__ int sh[SCAN_B];
    const int i = blockIdx.x * SCAN_B + threadIdx.x;
    int v = (i < n) ? counts[i] : 0;
    sh[threadIdx.x] = v;
    __syncthreads();
#pragma unroll
    for (int off = 1; off < SCAN_B; off <<= 1) {
        int t = (threadIdx.x >= off) ? sh[threadIdx.x - off] : 0;
        __syncthreads();
        sh[threadIdx.x] += t;
        __syncthreads();
    }
    if (i < n) rowPtr[i] = sh[threadIdx.x] - v;      // exclusive
    if (threadIdx.x == SCAN_B - 1) blockSums[blockIdx.x] = sh[SCAN_B - 1];
}

__global__ void scan2_kernel(int* __restrict__ blockSums, int nb)
{
    __shared__ int sh[512];
    int v = (threadIdx.x < nb) ? blockSums[threadIdx.x] : 0;
    sh[threadIdx.x] = v;
    __syncthreads();
#pragma unroll
    for (int off = 1; off < 512; off <<= 1) {
        int t = (threadIdx.x >= off) ? sh[threadIdx.x - off] : 0;
        __syncthreads();
        sh[threadIdx.x] += t;
        __syncthreads();
    }
    if (threadIdx.x < nb) blockSums[threadIdx.x] = sh[threadIdx.x] - v;  // exclusive
}

__global__ void scan3_kernel(int* __restrict__ rowPtr, const int* __restrict__ blockSums,
                             int* __restrict__ wptr, int n, int total)
{
    const int i = blockIdx.x * SCAN_B + threadIdx.x;
    if (i < n) {
        const int p = rowPtr[i] + blockSums[blockIdx.x];
        rowPtr[i] = p;
        wptr[i]   = p;
    }
    if (i == 0) rowPtr[n] = total;
}

// Pack (col, val) into one uint32: fp16 val bits (sign always 0 for val in
// [0,1)) in bits [31:17], col (< 2^17) in bits [16:0].
__global__ void scatter_kernel(const int* __restrict__ rows, const int* __restrict__ cols,
                               const float* __restrict__ vals, int* __restrict__ wptr,
                               unsigned* __restrict__ csr, int E)
{
    for (int e = blockIdx.x * blockDim.x + threadIdx.x; e < E; e += gridDim.x * blockDim.x) {
        const int r = rows[e];
        const int pos = atomicAdd(&wptr[r], 1);
        const unsigned hb = (unsigned)__half_as_ushort(__float2half(vals[e]));
        csr[pos] = (hb << 17) | (unsigned)cols[e];
    }
}

// ---------------------------------------------------------------------------
// Row gather: plain 4-edge unrolled batches (R13-proven best).
// ---------------------------------------------------------------------------
__device__ __forceinline__ void unpack_edge(unsigned p, int& c, float& v)
{
    c = (int)(p & 0x1FFFFu);
    v = __half2float(__ushort_as_half((unsigned short)(p >> 17)));
}

__device__ __forceinline__ void edge_fma(
    const float4* __restrict__ S4, unsigned p, int lane, float acc[8])
{
    int c; float v;
    unpack_edge(p, c, v);
    const float4 raw = __ldg(&S4[(size_t)c * (HID / 8) + lane]);
    const __half2* h2 = (const __half2*)&raw;
#pragma unroll
    for (int q = 0; q < 4; q++) {
        float2 f = __half22float2(h2[q]);
        acc[q * 2 + 0] = fmaf(v, f.x, acc[q * 2 + 0]);
        acc[q * 2 + 1] = fmaf(v, f.y, acc[q * 2 + 1]);
    }
}

__device__ __forceinline__ void gather_row(
    const unsigned* __restrict__ csr, const float4* __restrict__ S4,
    int s, int e, int lane, float acc[8])
{
    int i = s;
    for (; i + 3 < e; i += 4) {
        unsigned p[4];
#pragma unroll
        for (int u = 0; u < 4; u++) p[u] = __ldg(&csr[i + u]);
        int   c[4];
        float v[4];
#pragma unroll
        for (int u = 0; u < 4; u++) unpack_edge(p[u], c[u], v[u]);
        float4 r[4];
#pragma unroll
        for (int u = 0; u < 4; u++)
            r[u] = __ldg(&S4[(size_t)c[u] * (HID / 8) + lane]);
#pragma unroll
        for (int u = 0; u < 4; u++) {
            const __half2* h2 = (const __half2*)&r[u];
#pragma unroll
            for (int q = 0; q < 4; q++) {
                float2 f = __half22float2(h2[q]);
                acc[q * 2 + 0] = fmaf(v[u], f.x, acc[q * 2 + 0]);
                acc[q * 2 + 1] = fmaf(v[u], f.y, acc[q * 2 + 1]);
            }
        }
    }
    for (; i < e; i++)
        edge_fma(S4, __ldg(&csr[i]), lane, acc);
}

// ---------------------------------------------------------------------------
// SpMM: CSR gather from fp16 source, fused bias (+optional relu), fp16 out.
// One warp per destination node in [base, base+count); lane owns 8 cols.
// Output stores are streaming (__stcs) so the write stream does not evict
// the L2-resident gather source S.
// ---------------------------------------------------------------------------
template <bool RELU>
__global__ __launch_bounds__(256) void spmm_kernel(
    const int* __restrict__ rowPtr, const unsigned* __restrict__ csr,
    const __half* __restrict__ S, const float* __restrict__ bias,
    __half* __restrict__ Hout, int base, int count)
{
    const int w = (blockIdx.x * blockDim.x + threadIdx.x) >> 5;
    const int lane = threadIdx.x & 31;
    if (w >= count) return;
    const int node = base + w;

    const int s = rowPtr[node];
    const int e = rowPtr[node + 1];

    float acc[8];
#pragma unroll
    for (int j = 0; j < 8; j++) acc[j] = 0.f;

    const float4* __restrict__ S4 = (const float4*)S;
    gather_row(csr, S4, s, e, lane, acc);

    const float4* __restrict__ b4 = (const float4*)bias;
    const float4 bb0 = __ldg(&b4[lane * 2 + 0]);
    const float4 bb1 = __ldg(&b4[lane * 2 + 1]);
#pragma unroll
    for (int q = 0; q < 4; q++) {
        acc[q]     += ((const float*)&bb0)[q];
        acc[q + 4] += ((const float*)&bb1)[q];
    }
    if (RELU) {
#pragma unroll
        for (int j = 0; j < 8; j++) acc[j] = fmaxf(acc[j], 0.f);
    }

    __half2 h0 = __float22half2_rn(make_float2(acc[0], acc[1]));
    __half2 h1 = __float22half2_rn(make_float2(acc[2], acc[3]));
    __half2 h2 = __float22half2_rn(make_float2(acc[4], acc[5]));
    __half2 h3 = __float22half2_rn(make_float2(acc[6], acc[7]));
    uint4 packed;
    packed.x = *(unsigned*)&h0; packed.y = *(unsigned*)&h1;
    packed.z = *(unsigned*)&h2; packed.w = *(unsigned*)&h3;
    __stcs((uint4*)(Hout + (size_t)node * HID) + lane, packed);
}

// ---------------------------------------------------------------------------
// Tensor-core head over node range [base, base+count): a = relu(L @ fc1W +
// fc1b); z = a @ fc2W + fc2b; out = log_softmax(z). 64 nodes/block, 4 warps.
// ---------------------------------------------------------------------------
__global__ __launch_bounds__(128) void head_wmma_kernel(
    const __half* __restrict__ L,
    const float* __restrict__ fc1W, const float* __restrict__ fc1b,
    const float* __restrict__ fc2W, const float* __restrict__ fc2b,
    float* __restrict__ out, int base, int count)
{
    __shared__ __half Bw[HID][40];          // fc1W fp16, padded stride
    __shared__ float  stage[4][16 * 36];    // per-warp fp32 staging, ldm 36

    const int tid = threadIdx.x;
    for (int i = tid; i < HID * 32; i += blockDim.x) {
        const int r = i >> 5;
        const int c = i & 31;
        Bw[r][c] = __float2half(fc1W[i]);
    }
    __syncthreads();

    const int w = tid >> 5;
    const int lane = tid & 31;
    const int rowBase = base + blockIdx.x * 64 + w * 16;

    wmma::fragment<wmma::accumulator, 16, 16, 16, float> acc0, acc1;
    wmma::fill_fragment(acc0, 0.f);
    wmma::fill_fragment(acc1, 0.f);

    const __half* Abase = L + (size_t)rowBase * HID;
#pragma unroll
    for (int kk = 0; kk < HID; kk += 16) {
        wmma::fragment<wmma::matrix_a, 16, 16, 16, __half, wmma::row_major> af;
        wmma::fragment<wmma::matrix_b, 16, 16, 16, __half, wmma::row_major> bf0, bf1;
        wmma::load_matrix_sync(af, Abase + kk, HID);
        wmma::load_matrix_sync(bf0, &Bw[kk][0], 40);
        wmma::load_matrix_sync(bf1, &Bw[kk][16], 40);
        wmma::mma_sync(acc0, af, bf0, acc0);
        wmma::mma_sync(acc1, af, bf1, acc1);
    }

    float* st = &stage[w][0];
    wmma::store_matrix_sync(st,      acc0, 36, wmma::mem_row_major);
    wmma::store_matrix_sync(st + 16, acc1, 36, wmma::mem_row_major);
    __syncwarp();

    const float b1a = __ldg(&fc1b[lane]);
    const float w2a = __ldg(&fc2W[lane * 2 + 0]);
    const float w2b = __ldg(&fc2W[lane * 2 + 1]);
    const float zb0 = __ldg(&fc2b[0]);
    const float zb1 = __ldg(&fc2b[1]);

#pragma unroll 4
    for (int r = 0; r < 16; r++) {
        const int node = rowBase + r;
        float a = fmaxf(st[r * 36 + lane] + b1a, 0.f);
        float t0 = a * w2a;
        float t1 = a * w2b;
#pragma unroll
        for (int off = 16; off > 0; off >>= 1) {
            t0 += __shfl_down_sync(0xffffffffu, t0, off);
            t1 += __shfl_down_sync(0xffffffffu, t1, off);
        }
        if (lane == 0 && node < base + count) {
            const float z0 = t0 + zb0;
            const float z1 = t1 + zb1;
            const float m = fmaxf(z0, z1);
            const float lse = m + logf(expf(z0 - m) + expf(z1 - m));
            out[node * 2 + 0] = z0 - lse;
            out[node * 2 + 1] = z1 - lse;
        }
    }
}

// ---------------------------------------------------------------------------
extern "C" void kernel_launch(void* const* d_in, const int* in_sizes, int n_in,
                              void* d_out, int out_size)
{
    const float* inputs    = (const float*)d_in[0];
    const int*   edge_rows = (const int*)  d_in[1];
    const int*   edge_cols = (const int*)  d_in[2];
    const float* edge_vals = (const float*)d_in[3];
    const float* W1        = (const float*)d_in[4];
    const float* b1        = (const float*)d_in[5];
    const float* W2        = (const float*)d_in[6];
    const float* b2        = (const float*)d_in[7];
    const float* fc1W      = (const float*)d_in[8];
    const float* fc1b      = (const float*)d_in[9];
    const float* fc2W      = (const float*)d_in[10];
    const float* fc2b      = (const float*)d_in[11];
    float* out = (float*)d_out;

    const int N = in_sizes[0] / IN_DIM;   // 100000
    const int E = in_sizes[1];            // 3200000

    __half* bufS; __half* bufH; __half* W1h; __half* W2h;
    int* counts; int* rowPtr; int* blockSums; unsigned* csr;
    cudaGetSymbolAddress((void**)&bufS, g_bufS);
    cudaGetSymbolAddress((void**)&bufH, g_bufH);
    cudaGetSymbolAddress((void**)&W1h, g_W1h);
    cudaGetSymbolAddress((void**)&W2h, g_W2h);
    cudaGetSymbolAddress((void**)&counts, g_counts);
    cudaGetSymbolAddress((void**)&rowPtr, g_rowPtr);
    cudaGetSymbolAddress((void**)&blockSums, g_blockSums);
    cudaGetSymbolAddress((void**)&csr, g_csr);

    const int nScanBlocks = (N + SCAN_B - 1) / SCAN_B;   // 391

    // One-time creation of side stream + events (host objects only).
    static cudaStream_t s_side = nullptr;
    static cudaEvent_t  s_evFork = nullptr, s_evJoin = nullptr;
    static cudaEvent_t  s_evL2a = nullptr, s_evHeadA = nullptr;
    if (s_side == nullptr) {
        cudaStreamCreateWithFlags(&s_side, cudaStreamNonBlocking);
        cudaEventCreateWithFlags(&s_evFork, cudaEventDisableTiming);
        cudaEventCreateWithFlags(&s_evJoin, cudaEventDisableTiming);
        cudaEventCreateWithFlags(&s_evL2a, cudaEventDisableTiming);
        cudaEventCreateWithFlags(&s_evHeadA, cudaEventDisableTiming);
    }

    // ---- Fork: CSR build on side stream, weight convert + GEMM1 on main ----
    cudaEventRecord(s_evFork, 0);
    cudaStreamWaitEvent(s_side, s_evFork, 0);

    cudaMemsetAsync(counts, 0, (size_t)N * sizeof(int), s_side);
    histogram_kernel<<<512, 256, 0, s_side>>>(edge_rows, counts, E);
    scan1_kernel<<<nScanBlocks, SCAN_B, 0, s_side>>>(counts, rowPtr, blockSums, N);
    scan2_kernel<<<1, 512, 0, s_side>>>(blockSums, nScanBlocks);
    scan3_kernel<<<nScanBlocks, SCAN_B, 0, s_side>>>(rowPtr, blockSums, counts /*wptr*/, N, E);
    scatter_kernel<<<512, 256, 0, s_side>>>(edge_rows, edge_cols, edge_vals, counts, csr, E);
    cudaEventRecord(s_evJoin, s_side);

    const int gemmBlocks = (N + BM - 1) / BM;       // full-matrix GEMM blocks
    // Node split for the spmm2 / head pipeline (multiple of 64 for head tiles)
    const int NA2 = ((N / 2) / 64) * 64;            // 49984
    const int NB2 = N - NA2;

    // ---- Weight conversion, then Layer 1: S1 = f16(X @ W1h) ----
    convert_w_kernel<<<(IN_DIM * HID + 255) / 256, 256>>>(W1, W2, W1h, W2h);
    gemm_tc_kernel<float><<<gemmBlocks, 512>>>(inputs, W1h, bufS, N, IN_DIM, HID);

    // ---- Join: SpMM needs both S1 and the CSR ----
    cudaStreamWaitEvent(0, s_evJoin, 0);

    // H = f16(relu(spmm(S1) + b1))
    spmm_kernel<true><<<(N + 7) / 8, 256>>>(rowPtr, csr, bufS, b1, bufH, 0, N);

    // ---- Layer 2: S2 = f16(H @ W2h) ----
    gemm_tc_kernel<__half><<<gemmBlocks, 512>>>(bufH, W2h, bufS, N, HID, HID);

    // ---- spmm2 split into halves; head-a overlaps spmm2b ----
    // spmm2a: L rows [0, NA2)
    spmm_kernel<false><<<(NA2 + 7) / 8, 256>>>(rowPtr, csr, bufS, b2, bufH, 0, NA2);
    cudaEventRecord(s_evL2a, 0);

    // side: head-a on nodes [0, NA2) (tensor/smem-bound; overlaps spmm2b's L2)
    cudaStreamWaitEvent(s_side, s_evL2a, 0);
    head_wmma_kernel<<<NA2 / 64, 128, 0, s_side>>>(bufH, fc1W, fc1b, fc2W, fc2b,
                                                   out, 0, NA2);
    cudaEventRecord(s_evHeadA, s_side);

    // main: spmm2b on L rows [NA2, N), then head-b
    spmm_kernel<false><<<(NB2 + 7) / 8, 256>>>(rowPtr, csr, bufS, b2, bufH, NA2, NB2);
    head_wmma_kernel<<<(NB2 + 63) / 64, 128>>>(bufH, fc1W, fc1b, fc2W, fc2b,
                                               out, NA2, NB2);

    // Join head-a back into the main (capture-origin) stream.
    cudaStreamWaitEvent(0, s_evHeadA, 0);
}